// round 2
// baseline (speedup 1.0000x reference)
#include <cuda_runtime.h>
#include <cuda_bf16.h>

// ============================================================================
// GCN 2-layer on GB300.
//   Layer: out = D_in^-1/2 * A * D_out^-1/2 * x * W + b
// Rewritten (GEMM commutes with per-row scaling and with segment_sum):
//   A1 = (x @ W1) * dout_inv          [N,64]
//   B  = scatter_add(A1[src] -> dst)  [N,64]
//   h  = relu(B * din_inv + b1)       -> stored back into A
//   A2 = (h @ W2) * dout_inv          (in-place on A)
//   B  = scatter_add(A2[src] -> dst)  (B re-zeroed during relu pass)
//   out = B * din_inv + b2
// ============================================================================

#define NN 100000
#define FIN 128
#define FMID 64

__device__ int   g_deg_out[NN];
__device__ int   g_deg_in[NN];
__device__ float g_dinv_out[NN];
__device__ float g_dinv_in[NN];
__device__ float g_A[NN * FMID];   // gemm output / relu output
__device__ float g_B[NN * FMID];   // scatter accumulator

__device__ __forceinline__ void red_add_v4(float* addr, float4 v) {
    asm volatile("red.global.add.v4.f32 [%0], {%1,%2,%3,%4};"
                 :: "l"(addr), "f"(v.x), "f"(v.y), "f"(v.z), "f"(v.w)
                 : "memory");
}

// ---- zero scratch: B (N*16 float4) + degree counters ----
__global__ void k_zero(int n) {
    int t = blockIdx.x * blockDim.x + threadIdx.x;
    if (t < n * 16) {
        reinterpret_cast<float4*>(g_B)[t] = make_float4(0.f, 0.f, 0.f, 0.f);
    }
    if (t < n) {
        g_deg_out[t] = 0;
        g_deg_in[t]  = 0;
    }
}

// ---- degree histogram ----
__global__ void k_deg(const int* __restrict__ src, const int* __restrict__ dst, int E) {
    int e = blockIdx.x * blockDim.x + threadIdx.x;
    if (e < E) {
        atomicAdd(&g_deg_out[src[e]], 1);
        atomicAdd(&g_deg_in[dst[e]], 1);
    }
}

// ---- dinv = rsqrt(max(deg,1)) ----
__global__ void k_dinv(int n) {
    int i = blockIdx.x * blockDim.x + threadIdx.x;
    if (i < n) {
        g_dinv_out[i] = rsqrtf((float)max(g_deg_out[i], 1));
        g_dinv_in[i]  = rsqrtf((float)max(g_deg_in[i], 1));
    }
}

// ---- GEMM1: g_A[row] = (x[row] @ W1) * dinv_out[row]. Warp per row. ----
__global__ void k_gemm1(const float* __restrict__ x, const float* __restrict__ W1, int n) {
    __shared__ float sW[FIN * FMID];   // 32 KB
    int tid = threadIdx.x;
    for (int i = tid; i < FIN * FMID; i += blockDim.x) sW[i] = W1[i];
    __syncthreads();

    int lane = tid & 31;
    int warp = tid >> 5;
    int row = blockIdx.x * (blockDim.x >> 5) + warp;
    if (row >= n) return;

    const float* xr = x + (size_t)row * FIN;
    float xv0 = xr[lane];
    float xv1 = xr[lane + 32];
    float xv2 = xr[lane + 64];
    float xv3 = xr[lane + 96];

    float acc0 = 0.f, acc1 = 0.f;
#pragma unroll
    for (int k = 0; k < FIN; k++) {
        float xv;
        if (k < 32)       xv = __shfl_sync(0xffffffffu, xv0, k);
        else if (k < 64)  xv = __shfl_sync(0xffffffffu, xv1, k - 32);
        else if (k < 96)  xv = __shfl_sync(0xffffffffu, xv2, k - 64);
        else              xv = __shfl_sync(0xffffffffu, xv3, k - 96);
        acc0 += xv * sW[k * FMID + lane];
        acc1 += xv * sW[k * FMID + lane + 32];
    }
    float s = g_dinv_out[row];
    g_A[(size_t)row * FMID + lane]      = acc0 * s;
    g_A[(size_t)row * FMID + lane + 32] = acc1 * s;
}

// ---- GEMM2 (in-place): g_A[row] = (g_A[row] @ W2) * dinv_out[row] ----
__global__ void k_gemm2(const float* __restrict__ W2, int n) {
    __shared__ float sW[FMID * FMID];  // 16 KB
    int tid = threadIdx.x;
    for (int i = tid; i < FMID * FMID; i += blockDim.x) sW[i] = W2[i];
    __syncthreads();

    int lane = tid & 31;
    int warp = tid >> 5;
    int row = blockIdx.x * (blockDim.x >> 5) + warp;
    if (row >= n) return;

    float* ar = g_A + (size_t)row * FMID;
    float x0 = ar[lane];
    float x1 = ar[lane + 32];

    float acc0 = 0.f, acc1 = 0.f;
#pragma unroll
    for (int k = 0; k < FMID; k++) {
        float xv = __shfl_sync(0xffffffffu, (k < 32) ? x0 : x1, k & 31);
        acc0 += xv * sW[k * FMID + lane];
        acc1 += xv * sW[k * FMID + lane + 32];
    }
    float s = g_dinv_out[row];
    ar[lane]      = acc0 * s;
    ar[lane + 32] = acc1 * s;
}

// ---- edge scatter: B[dst] += A[src], 16 threads (float4 each) per edge ----
__global__ void k_scatter(const int* __restrict__ src, const int* __restrict__ dst, int E) {
    int t = blockIdx.x * blockDim.x + threadIdx.x;
    int e = t >> 4;
    if (e >= E) return;
    int j = (t & 15) * 4;
    int s = src[e];
    int d = dst[e];
    float4 v = *reinterpret_cast<const float4*>(g_A + (size_t)s * FMID + j);
    red_add_v4(g_B + (size_t)d * FMID + j, v);
}

// ---- relu epilogue of layer 1: A = relu(B*din + b1); also re-zero B ----
__global__ void k_relu_rezero(const float* __restrict__ b1, int n) {
    int t = blockIdx.x * blockDim.x + threadIdx.x;
    if (t >= n * 16) return;
    int row = t >> 4;
    int j = (t & 15) * 4;
    float s = g_dinv_in[row];
    float4 v  = *reinterpret_cast<float4*>(g_B + (size_t)row * FMID + j);
    float4 bb = *reinterpret_cast<const float4*>(b1 + j);
    v.x = fmaxf(fmaf(v.x, s, bb.x), 0.f);
    v.y = fmaxf(fmaf(v.y, s, bb.y), 0.f);
    v.z = fmaxf(fmaf(v.z, s, bb.z), 0.f);
    v.w = fmaxf(fmaf(v.w, s, bb.w), 0.f);
    *reinterpret_cast<float4*>(g_A + (size_t)row * FMID + j) = v;
    *reinterpret_cast<float4*>(g_B + (size_t)row * FMID + j) = make_float4(0.f, 0.f, 0.f, 0.f);
}

// ---- final epilogue: out = B*din + b2 ----
__global__ void k_final(const float* __restrict__ b2, float* __restrict__ out, int n) {
    int t = blockIdx.x * blockDim.x + threadIdx.x;
    if (t >= n * 16) return;
    int row = t >> 4;
    int j = (t & 15) * 4;
    float s = g_dinv_in[row];
    float4 v  = *reinterpret_cast<float4*>(g_B + (size_t)row * FMID + j);
    float4 bb = *reinterpret_cast<const float4*>(b2 + j);
    v.x = fmaf(v.x, s, bb.x);
    v.y = fmaf(v.y, s, bb.y);
    v.z = fmaf(v.z, s, bb.z);
    v.w = fmaf(v.w, s, bb.w);
    *reinterpret_cast<float4*>(out + (size_t)row * FMID + j) = v;
}

extern "C" void kernel_launch(void* const* d_in, const int* in_sizes, int n_in,
                              void* d_out, int out_size) {
    const float* x   = (const float*)d_in[0];
    const int*   src = (const int*)d_in[1];
    const int*   dst = (const int*)d_in[2];
    const float* W1  = (const float*)d_in[3];
    const float* b1  = (const float*)d_in[4];
    const float* W2  = (const float*)d_in[5];
    const float* b2  = (const float*)d_in[6];
    float* out = (float*)d_out;

    const int n = NN;
    const int E = in_sizes[1];

    const int T = 256;
    int grid_nodes16 = (n * 16 + T - 1) / T;     // N*16 float4-threads
    int grid_edges   = (E + T - 1) / T;
    int grid_nodes   = (n + T - 1) / T;
    int grid_rows    = (n + (T >> 5) - 1) / (T >> 5);   // warp per row
    int grid_scat    = (E * 16 + T - 1) / T;

    k_zero<<<grid_nodes16, T>>>(n);
    k_deg<<<grid_edges, T>>>(src, dst, E);
    k_dinv<<<grid_nodes, T>>>(n);

    k_gemm1<<<grid_rows, T>>>(x, W1, n);
    k_scatter<<<grid_scat, T>>>(src, dst, E);
    k_relu_rezero<<<grid_nodes16, T>>>(b1, n);

    k_gemm2<<<grid_rows, T>>>(W2, n);
    k_scatter<<<grid_scat, T>>>(src, dst, E);
    k_final<<<grid_nodes16, T>>>(b2, out, n);
}

// round 4
// speedup vs baseline: 1.3336x; 1.3336x over previous
#include <cuda_runtime.h>
#include <cuda_bf16.h>

// ============================================================================
// GCN 2-layer on GB300, round 2.
//   A1 = (x @ W1) * dout_inv            [tiled SGEMM -> g_A]
//   CSR build (deg -> scan -> fill)
//   h  = relu(gather_sum(A1) * din_inv + b1)   [CSR gather -> g_B]
//   A2 = (h @ W2) * dout_inv            [tiled SGEMM -> g_A]
//   out = gather_sum(A2) * din_inv + b2        [CSR gather -> d_out]
// ============================================================================

#define NN   100000
#define EMAX 1600000
#define FMID 64

__device__ int   g_deg_out[NN];
__device__ int   g_deg_in[NN];
__device__ float g_dinv_out[NN];
__device__ float g_dinv_in[NN];
__device__ int   g_csr_ptr[NN + 1];
__device__ int   g_cursor[NN];
__device__ int   g_csr_src[EMAX];
__device__ float g_A[NN * FMID];   // gemm outputs
__device__ float g_B[NN * FMID];   // layer-1 hidden (relu output)

// ---- zero degree counters ----
__global__ void k_zero(int n) {
    int t = blockIdx.x * blockDim.x + threadIdx.x;
    if (t < n) { g_deg_out[t] = 0; g_deg_in[t] = 0; }
}

// ---- degree histogram ----
__global__ void k_deg(const int* __restrict__ src, const int* __restrict__ dst, int E) {
    int e = blockIdx.x * blockDim.x + threadIdx.x;
    if (e < E) {
        atomicAdd(&g_deg_out[src[e]], 1);
        atomicAdd(&g_deg_in[dst[e]], 1);
    }
}

// ---- dinv = rsqrt(max(deg,1)) ----
__global__ void k_dinv(int n) {
    int i = blockIdx.x * blockDim.x + threadIdx.x;
    if (i < n) {
        g_dinv_out[i] = rsqrtf((float)max(g_deg_out[i], 1));
        g_dinv_in[i]  = rsqrtf((float)max(g_deg_in[i], 1));
    }
}

// ---- single-block exclusive scan of g_deg_in -> g_csr_ptr (+cursor copy) ----
__global__ void k_scan() {
    __shared__ int s[1024];
    const int t = threadIdx.x;
    const int CH = (NN + 1023) / 1024;       // 98
    int start = t * CH;
    int end   = min(start + CH, NN);
    int sum = 0;
    for (int i = start; i < end; i++) sum += g_deg_in[i];
    s[t] = sum;
    __syncthreads();
    // inclusive Hillis-Steele scan
    for (int off = 1; off < 1024; off <<= 1) {
        int v = (t >= off) ? s[t - off] : 0;
        __syncthreads();
        s[t] += v;
        __syncthreads();
    }
    int run = (t == 0) ? 0 : s[t - 1];       // exclusive prefix
    for (int i = start; i < end; i++) {
        g_csr_ptr[i] = run;
        g_cursor[i]  = run;
        run += g_deg_in[i];
    }
    if (t == 1023) g_csr_ptr[NN] = s[1023];
}

// ---- CSR fill: bucket src ids by dst ----
__global__ void k_fill(const int* __restrict__ src, const int* __restrict__ dst, int E) {
    int e = blockIdx.x * blockDim.x + threadIdx.x;
    if (e < E) {
        int pos = atomicAdd(&g_cursor[dst[e]], 1);
        g_csr_src[pos] = src[e];
    }
}

// ============================================================================
// Tiled SGEMM: out[r,c] = (X[r,:] @ W[:,c]) * dinv_out[r]
// Block tile 128 rows x 64 cols, 256 threads, 8x4 accumulators per thread.
// K chunked by 32. FROM_B: read input from g_B instead of X arg. Writes g_A.
// ============================================================================
template<int K, bool FROM_B>
__global__ void k_gemm(const float* __restrict__ Xarg, const float* __restrict__ W, int n) {
    __shared__ float sXT[32][132];   // transposed x chunk (padded)
    __shared__ float sW[32][64];

    const float* __restrict__ X = FROM_B ? (const float*)g_B : Xarg;

    int tid = threadIdx.x;
    int tx = tid & 15;        // col group: cols tx*4 .. tx*4+3
    int ty = tid >> 4;        // row group: rows ty*8 .. ty*8+7
    int row0 = blockIdx.x * 128;

    float acc[8][4];
#pragma unroll
    for (int r = 0; r < 8; r++)
#pragma unroll
        for (int c = 0; c < 4; c++) acc[r][c] = 0.f;

    for (int kc = 0; kc < K; kc += 32) {
        // load W chunk [32][64]
#pragma unroll
        for (int p = 0; p < 8; p++) {
            int idx = tid + p * 256;
            int k = idx >> 6, c = idx & 63;
            sW[k][c] = W[(size_t)(kc + k) * 64 + c];
        }
        // load X chunk [128 rows][32 k] transposed into sXT
#pragma unroll
        for (int p = 0; p < 4; p++) {
            int l = tid + p * 256;        // float4 slot, 0..1023
            int r = l >> 3;               // tile row 0..127
            int kk = (l & 7) << 2;        // k offset 0,4,..,28
            float4 v = make_float4(0.f, 0.f, 0.f, 0.f);
            int gr = row0 + r;
            if (gr < n)
                v = *reinterpret_cast<const float4*>(X + (size_t)gr * K + kc + kk);
            sXT[kk + 0][r] = v.x;
            sXT[kk + 1][r] = v.y;
            sXT[kk + 2][r] = v.z;
            sXT[kk + 3][r] = v.w;
        }
        __syncthreads();

#pragma unroll
        for (int k = 0; k < 32; k++) {
            float4 xa = *reinterpret_cast<float4*>(&sXT[k][ty * 8]);
            float4 xb = *reinterpret_cast<float4*>(&sXT[k][ty * 8 + 4]);
            float4 wv = *reinterpret_cast<float4*>(&sW[k][tx * 4]);
            float xr[8] = {xa.x, xa.y, xa.z, xa.w, xb.x, xb.y, xb.z, xb.w};
            float wc[4] = {wv.x, wv.y, wv.z, wv.w};
#pragma unroll
            for (int r = 0; r < 8; r++)
#pragma unroll
                for (int c = 0; c < 4; c++)
                    acc[r][c] = fmaf(xr[r], wc[c], acc[r][c]);
        }
        __syncthreads();
    }

#pragma unroll
    for (int r = 0; r < 8; r++) {
        int gr = row0 + ty * 8 + r;
        if (gr < n) {
            float s = g_dinv_out[gr];
            float4 o = make_float4(acc[r][0] * s, acc[r][1] * s,
                                   acc[r][2] * s, acc[r][3] * s);
            *reinterpret_cast<float4*>(g_A + (size_t)gr * 64 + tx * 4) = o;
        }
    }
}

// ============================================================================
// CSR aggregate + fused epilogue. Warp per node, lane owns 2 feature cols.
// Reads g_A. LAYER==1: write relu(acc*din+b1) to g_B. LAYER==2: acc*din+b2 -> out.
// ============================================================================
template<int LAYER>
__global__ void k_agg(const float* __restrict__ bias, float* __restrict__ outp, int n) {
    int gw = (blockIdx.x * blockDim.x + threadIdx.x) >> 5;
    int lane = threadIdx.x & 31;
    if (gw >= n) return;

    int s0 = g_csr_ptr[gw];
    int s1 = g_csr_ptr[gw + 1];

    float ax = 0.f, ay = 0.f;
    for (int base = s0; base < s1; base += 32) {
        int cnt = min(32, s1 - base);
        int e = (lane < cnt) ? g_csr_src[base + lane] : 0;
        int j = 0;
        for (; j + 3 < cnt; j += 4) {
            int s_0 = __shfl_sync(0xffffffffu, e, j + 0);
            int s_1 = __shfl_sync(0xffffffffu, e, j + 1);
            int s_2 = __shfl_sync(0xffffffffu, e, j + 2);
            int s_3 = __shfl_sync(0xffffffffu, e, j + 3);
            float2 a0 = *reinterpret_cast<const float2*>(g_A + (size_t)s_0 * 64 + lane * 2);
            float2 a1 = *reinterpret_cast<const float2*>(g_A + (size_t)s_1 * 64 + lane * 2);
            float2 a2 = *reinterpret_cast<const float2*>(g_A + (size_t)s_2 * 64 + lane * 2);
            float2 a3 = *reinterpret_cast<const float2*>(g_A + (size_t)s_3 * 64 + lane * 2);
            ax += a0.x + a1.x + a2.x + a3.x;
            ay += a0.y + a1.y + a2.y + a3.y;
        }
        for (; j < cnt; j++) {
            int ss = __shfl_sync(0xffffffffu, e, j);
            float2 a = *reinterpret_cast<const float2*>(g_A + (size_t)ss * 64 + lane * 2);
            ax += a.x;
            ay += a.y;
        }
    }

    float sc = g_dinv_in[gw];
    float bx = bias[lane * 2];
    float by = bias[lane * 2 + 1];
    float ox = fmaf(ax, sc, bx);
    float oy = fmaf(ay, sc, by);
    if (LAYER == 1) {
        ox = fmaxf(ox, 0.f);
        oy = fmaxf(oy, 0.f);
        *reinterpret_cast<float2*>(g_B + (size_t)gw * 64 + lane * 2) = make_float2(ox, oy);
    } else {
        *reinterpret_cast<float2*>(outp + (size_t)gw * 64 + lane * 2) = make_float2(ox, oy);
    }
}

extern "C" void kernel_launch(void* const* d_in, const int* in_sizes, int n_in,
                              void* d_out, int out_size) {
    const float* x   = (const float*)d_in[0];
    const int*   src = (const int*)d_in[1];
    const int*   dst = (const int*)d_in[2];
    const float* W1  = (const float*)d_in[3];
    const float* b1  = (const float*)d_in[4];
    const float* W2  = (const float*)d_in[5];
    const float* b2  = (const float*)d_in[6];
    float* out = (float*)d_out;

    const int n = NN;
    const int E = in_sizes[1];

    const int T = 256;
    int grid_edges = (E + T - 1) / T;
    int grid_nodes = (n + T - 1) / T;
    int grid_gemm  = (n + 127) / 128;
    int grid_agg   = (n * 32 + T - 1) / T;   // warp per node

    // graph prep
    k_zero<<<grid_nodes, T>>>(n);
    k_deg<<<grid_edges, T>>>(src, dst, E);
    k_dinv<<<grid_nodes, T>>>(n);
    k_scan<<<1, 1024>>>();
    k_fill<<<grid_edges, T>>>(src, dst, E);

    // layer 1
    k_gemm<128, false><<<grid_gemm, T>>>(x, W1, n);
    k_agg<1><<<grid_agg, T>>>(b1, nullptr, n);

    // layer 2
    k_gemm<64, true><<<grid_gemm, T>>>(nullptr, W2, n);
    k_agg<2><<<grid_agg, T>>>(b2, out, n);
}

// round 5
// speedup vs baseline: 2.3949x; 1.7958x over previous
#include <cuda_runtime.h>
#include <cuda_bf16.h>

// ============================================================================
// GCN 2-layer on GB300, round 4: hierarchical scan (was 161us single-block).
//   A1 = (x @ W1) * dout_inv            [tiled SGEMM -> g_A]
//   CSR build (deg -> 3-phase scan -> fill)
//   h  = relu(gather_sum(A1) * din_inv + b1)   [CSR gather -> g_B]
//   A2 = (h @ W2) * dout_inv            [tiled SGEMM -> g_A]
//   out = gather_sum(A2) * din_inv + b2        [CSR gather -> d_out]
// ============================================================================

#define NN   100000
#define EMAX 1600000
#define FMID 64
#define SCAN_CHUNK 2048
#define NBLK ((NN + SCAN_CHUNK - 1) / SCAN_CHUNK)   // 49

__device__ int   g_deg_out[NN];
__device__ int   g_deg_in[NN];
__device__ float g_dinv_out[NN];
__device__ float g_dinv_in[NN];
__device__ int   g_csr_ptr[NN + 1];
__device__ int   g_cursor[NN];
__device__ int   g_csr_src[EMAX];
__device__ int   g_bsum[NBLK];
__device__ int   g_boff[NBLK];
__device__ float g_A[NN * FMID];   // gemm outputs
__device__ float g_B[NN * FMID];   // layer-1 hidden (relu output)

// ---- zero degree counters ----
__global__ void k_zero(int n) {
    int t = blockIdx.x * blockDim.x + threadIdx.x;
    if (t < n) { g_deg_out[t] = 0; g_deg_in[t] = 0; }
}

// ---- degree histogram ----
__global__ void k_deg(const int* __restrict__ src, const int* __restrict__ dst, int E) {
    int e = blockIdx.x * blockDim.x + threadIdx.x;
    if (e < E) {
        atomicAdd(&g_deg_out[src[e]], 1);
        atomicAdd(&g_deg_in[dst[e]], 1);
    }
}

// ---- dinv = rsqrt(max(deg,1)) ----
__global__ void k_dinv(int n) {
    int i = blockIdx.x * blockDim.x + threadIdx.x;
    if (i < n) {
        g_dinv_out[i] = rsqrtf((float)max(g_deg_out[i], 1));
        g_dinv_in[i]  = rsqrtf((float)max(g_deg_in[i], 1));
    }
}

// ---- scan phase 1: block-local exclusive scan (2 elems/thread) + block sums ----
__global__ void k_scan1() {
    __shared__ int s[1024];
    int t = threadIdx.x;
    int base = blockIdx.x * SCAN_CHUNK;
    int i0 = base + t * 2;
    int i1 = i0 + 1;
    int v0 = (i0 < NN) ? g_deg_in[i0] : 0;
    int v1 = (i1 < NN) ? g_deg_in[i1] : 0;
    s[t] = v0 + v1;
    __syncthreads();
#pragma unroll
    for (int off = 1; off < 1024; off <<= 1) {
        int v = (t >= off) ? s[t - off] : 0;
        __syncthreads();
        s[t] += v;
        __syncthreads();
    }
    int excl = (t == 0) ? 0 : s[t - 1];
    if (i0 < NN) g_csr_ptr[i0] = excl;
    if (i1 < NN) g_csr_ptr[i1] = excl + v0;
    if (t == 1023) g_bsum[blockIdx.x] = s[1023];
}

// ---- scan phase 2: exclusive scan of the NBLK block sums (one tiny block) ----
__global__ void k_scan2() {
    __shared__ int s[64];
    int t = threadIdx.x;
    int v = (t < NBLK) ? g_bsum[t] : 0;
    s[t] = v;
    __syncthreads();
#pragma unroll
    for (int off = 1; off < 64; off <<= 1) {
        int u = (t >= off) ? s[t - off] : 0;
        __syncthreads();
        s[t] += u;
        __syncthreads();
    }
    if (t < NBLK) g_boff[t] = (t == 0) ? 0 : s[t - 1];
}

// ---- scan phase 3: add block offsets, mirror to cursor, set sentinel ----
__global__ void k_scan3(int E) {
    int i = blockIdx.x * blockDim.x + threadIdx.x;
    if (i < NN) {
        int v = g_csr_ptr[i] + g_boff[i / SCAN_CHUNK];
        g_csr_ptr[i] = v;
        g_cursor[i]  = v;
    }
    if (i == 0) g_csr_ptr[NN] = E;   // total in-degree == E
}

// ---- CSR fill: bucket src ids by dst ----
__global__ void k_fill(const int* __restrict__ src, const int* __restrict__ dst, int E) {
    int e = blockIdx.x * blockDim.x + threadIdx.x;
    if (e < E) {
        int pos = atomicAdd(&g_cursor[dst[e]], 1);
        g_csr_src[pos] = src[e];
    }
}

// ============================================================================
// Tiled SGEMM: out[r,c] = (X[r,:] @ W[:,c]) * dinv_out[r]
// Block tile 128 rows x 64 cols, 256 threads, 8x4 accumulators per thread.
// ============================================================================
template<int K, bool FROM_B>
__global__ void k_gemm(const float* __restrict__ Xarg, const float* __restrict__ W, int n) {
    __shared__ float sXT[32][132];   // transposed x chunk (padded)
    __shared__ float sW[32][64];

    const float* __restrict__ X = FROM_B ? (const float*)g_B : Xarg;

    int tid = threadIdx.x;
    int tx = tid & 15;
    int ty = tid >> 4;
    int row0 = blockIdx.x * 128;

    float acc[8][4];
#pragma unroll
    for (int r = 0; r < 8; r++)
#pragma unroll
        for (int c = 0; c < 4; c++) acc[r][c] = 0.f;

    for (int kc = 0; kc < K; kc += 32) {
#pragma unroll
        for (int p = 0; p < 8; p++) {
            int idx = tid + p * 256;
            int k = idx >> 6, c = idx & 63;
            sW[k][c] = W[(size_t)(kc + k) * 64 + c];
        }
#pragma unroll
        for (int p = 0; p < 4; p++) {
            int l = tid + p * 256;
            int r = l >> 3;
            int kk = (l & 7) << 2;
            float4 v = make_float4(0.f, 0.f, 0.f, 0.f);
            int gr = row0 + r;
            if (gr < n)
                v = *reinterpret_cast<const float4*>(X + (size_t)gr * K + kc + kk);
            sXT[kk + 0][r] = v.x;
            sXT[kk + 1][r] = v.y;
            sXT[kk + 2][r] = v.z;
            sXT[kk + 3][r] = v.w;
        }
        __syncthreads();

#pragma unroll
        for (int k = 0; k < 32; k++) {
            float4 xa = *reinterpret_cast<float4*>(&sXT[k][ty * 8]);
            float4 xb = *reinterpret_cast<float4*>(&sXT[k][ty * 8 + 4]);
            float4 wv = *reinterpret_cast<float4*>(&sW[k][tx * 4]);
            float xr[8] = {xa.x, xa.y, xa.z, xa.w, xb.x, xb.y, xb.z, xb.w};
            float wc[4] = {wv.x, wv.y, wv.z, wv.w};
#pragma unroll
            for (int r = 0; r < 8; r++)
#pragma unroll
                for (int c = 0; c < 4; c++)
                    acc[r][c] = fmaf(xr[r], wc[c], acc[r][c]);
        }
        __syncthreads();
    }

#pragma unroll
    for (int r = 0; r < 8; r++) {
        int gr = row0 + ty * 8 + r;
        if (gr < n) {
            float s = g_dinv_out[gr];
            float4 o = make_float4(acc[r][0] * s, acc[r][1] * s,
                                   acc[r][2] * s, acc[r][3] * s);
            *reinterpret_cast<float4*>(g_A + (size_t)gr * 64 + tx * 4) = o;
        }
    }
}

// ============================================================================
// CSR aggregate + fused epilogue. Warp per node, lane owns 2 feature cols.
// ============================================================================
template<int LAYER>
__global__ void k_agg(const float* __restrict__ bias, float* __restrict__ outp, int n) {
    int gw = (blockIdx.x * blockDim.x + threadIdx.x) >> 5;
    int lane = threadIdx.x & 31;
    if (gw >= n) return;

    int s0 = g_csr_ptr[gw];
    int s1 = g_csr_ptr[gw + 1];

    float ax = 0.f, ay = 0.f;
    for (int base = s0; base < s1; base += 32) {
        int cnt = min(32, s1 - base);
        int e = (lane < cnt) ? g_csr_src[base + lane] : 0;
        int j = 0;
        for (; j + 3 < cnt; j += 4) {
            int s_0 = __shfl_sync(0xffffffffu, e, j + 0);
            int s_1 = __shfl_sync(0xffffffffu, e, j + 1);
            int s_2 = __shfl_sync(0xffffffffu, e, j + 2);
            int s_3 = __shfl_sync(0xffffffffu, e, j + 3);
            float2 a0 = *reinterpret_cast<const float2*>(g_A + (size_t)s_0 * 64 + lane * 2);
            float2 a1 = *reinterpret_cast<const float2*>(g_A + (size_t)s_1 * 64 + lane * 2);
            float2 a2 = *reinterpret_cast<const float2*>(g_A + (size_t)s_2 * 64 + lane * 2);
            float2 a3 = *reinterpret_cast<const float2*>(g_A + (size_t)s_3 * 64 + lane * 2);
            ax += a0.x + a1.x + a2.x + a3.x;
            ay += a0.y + a1.y + a2.y + a3.y;
        }
        for (; j < cnt; j++) {
            int ss = __shfl_sync(0xffffffffu, e, j);
            float2 a = *reinterpret_cast<const float2*>(g_A + (size_t)ss * 64 + lane * 2);
            ax += a.x;
            ay += a.y;
        }
    }

    float sc = g_dinv_in[gw];
    float bx = bias[lane * 2];
    float by = bias[lane * 2 + 1];
    float ox = fmaf(ax, sc, bx);
    float oy = fmaf(ay, sc, by);
    if (LAYER == 1) {
        ox = fmaxf(ox, 0.f);
        oy = fmaxf(oy, 0.f);
        *reinterpret_cast<float2*>(g_B + (size_t)gw * 64 + lane * 2) = make_float2(ox, oy);
    } else {
        *reinterpret_cast<float2*>(outp + (size_t)gw * 64 + lane * 2) = make_float2(ox, oy);
    }
}

extern "C" void kernel_launch(void* const* d_in, const int* in_sizes, int n_in,
                              void* d_out, int out_size) {
    const float* x   = (const float*)d_in[0];
    const int*   src = (const int*)d_in[1];
    const int*   dst = (const int*)d_in[2];
    const float* W1  = (const float*)d_in[3];
    const float* b1  = (const float*)d_in[4];
    const float* W2  = (const float*)d_in[5];
    const float* b2  = (const float*)d_in[6];
    float* out = (float*)d_out;

    const int n = NN;
    const int E = in_sizes[1];

    const int T = 256;
    int grid_edges = (E + T - 1) / T;
    int grid_nodes = (n + T - 1) / T;
    int grid_gemm  = (n + 127) / 128;
    int grid_agg   = (n * 32 + T - 1) / T;   // warp per node

    // graph prep
    k_zero<<<grid_nodes, T>>>(n);
    k_deg<<<grid_edges, T>>>(src, dst, E);
    k_dinv<<<grid_nodes, T>>>(n);
    k_scan1<<<NBLK, 1024>>>();
    k_scan2<<<1, 64>>>();
    k_scan3<<<grid_nodes, T>>>(E);
    k_fill<<<grid_edges, T>>>(src, dst, E);

    // layer 1
    k_gemm<128, false><<<grid_gemm, T>>>(x, W1, n);
    k_agg<1><<<grid_agg, T>>>(b1, nullptr, n);

    // layer 2
    k_gemm<64, true><<<grid_gemm, T>>>(nullptr, W2, n);
    k_agg<2><<<grid_agg, T>>>(b2, out, n);
}

// round 6
// speedup vs baseline: 2.7426x; 1.1452x over previous
#include <cuda_runtime.h>
#include <cuda_fp16.h>
#include <cuda_bf16.h>

// ============================================================================
// GCN 2-layer on GB300, round 5: fp16 HMMA gemms + fp16 gather matrix.
//   prep: deg -> dinv -> scan -> fill csr entries {src, dinv_out[src]}
//   A1h = fp16(x @ W1)                        [HMMA -> g_A half]
//   h   = relu(sum_src A1h[src]*dv[src] * din_inv + b1)  -> g_B half
//   A2h = fp16(h @ W2)                        [HMMA -> g_A half]
//   out = sum_src A2h[src]*dv[src] * din_inv + b2        -> d_out fp32
// ============================================================================

#define NN   100000
#define EMAX 1600000
#define SCAN_CHUNK 2048
#define NBLK ((NN + SCAN_CHUNK - 1) / SCAN_CHUNK)   // 49

__device__ int   g_deg_out[NN];
__device__ int   g_deg_in[NN];
__device__ float g_dinv_out[NN];
__device__ float g_dinv_in[NN];
__device__ int   g_csr_ptr[NN + 1];
__device__ int   g_cursor[NN];
__device__ int2  g_csr_ent[EMAX];                 // {src, dinv_out[src] bits}
__device__ int   g_bsum[NBLK];
__device__ int   g_boff[NBLK];
__device__ __align__(16) __half g_A[NN * 64];     // gemm outputs (unscaled)
__device__ __align__(16) __half g_B[NN * 64];     // layer-1 hidden (relu out)
__device__ __align__(16) __half g_W1t[64 * 128];  // W1^T [n][k] half
__device__ __align__(16) __half g_W2t[64 * 64];   // W2^T [n][k] half

// ---- zero degree counters ----
__global__ void k_zero(int n) {
    int t = blockIdx.x * blockDim.x + threadIdx.x;
    if (t < n) { g_deg_out[t] = 0; g_deg_in[t] = 0; }
}

// ---- degree histogram ----
__global__ void k_deg(const int* __restrict__ src, const int* __restrict__ dst, int E) {
    int e = blockIdx.x * blockDim.x + threadIdx.x;
    if (e < E) {
        atomicAdd(&g_deg_out[src[e]], 1);
        atomicAdd(&g_deg_in[dst[e]], 1);
    }
}

// ---- dinv = rsqrt(max(deg,1)) ----
__global__ void k_dinv(int n) {
    int i = blockIdx.x * blockDim.x + threadIdx.x;
    if (i < n) {
        g_dinv_out[i] = rsqrtf((float)max(g_deg_out[i], 1));
        g_dinv_in[i]  = rsqrtf((float)max(g_deg_in[i], 1));
    }
}

// ---- weight prep: transpose + fp16 convert. W[k][n] -> Wt[n][k] ----
__global__ void k_prepW(const float* __restrict__ W1, const float* __restrict__ W2) {
    int t = blockIdx.x * blockDim.x + threadIdx.x;
    if (t < 64 * 128) {
        int nn_ = t >> 7, k = t & 127;
        g_W1t[t] = __float2half(W1[k * 64 + nn_]);
    } else if (t < 64 * 128 + 64 * 64) {
        int u = t - 64 * 128;
        int nn_ = u >> 6, k = u & 63;
        g_W2t[u] = __float2half(W2[k * 64 + nn_]);
    }
}

// ---- scan phase 1: block-local exclusive scan (2 elems/thread) + block sums ----
__global__ void k_scan1() {
    __shared__ int s[1024];
    int t = threadIdx.x;
    int base = blockIdx.x * SCAN_CHUNK;
    int i0 = base + t * 2;
    int i1 = i0 + 1;
    int v0 = (i0 < NN) ? g_deg_in[i0] : 0;
    int v1 = (i1 < NN) ? g_deg_in[i1] : 0;
    s[t] = v0 + v1;
    __syncthreads();
#pragma unroll
    for (int off = 1; off < 1024; off <<= 1) {
        int v = (t >= off) ? s[t - off] : 0;
        __syncthreads();
        s[t] += v;
        __syncthreads();
    }
    int excl = (t == 0) ? 0 : s[t - 1];
    if (i0 < NN) g_csr_ptr[i0] = excl;
    if (i1 < NN) g_csr_ptr[i1] = excl + v0;
    if (t == 1023) g_bsum[blockIdx.x] = s[1023];
}

// ---- scan phase 2: exclusive scan of block sums ----
__global__ void k_scan2() {
    __shared__ int s[64];
    int t = threadIdx.x;
    int v = (t < NBLK) ? g_bsum[t] : 0;
    s[t] = v;
    __syncthreads();
#pragma unroll
    for (int off = 1; off < 64; off <<= 1) {
        int u = (t >= off) ? s[t - off] : 0;
        __syncthreads();
        s[t] += u;
        __syncthreads();
    }
    if (t < NBLK) g_boff[t] = (t == 0) ? 0 : s[t - 1];
}

// ---- scan phase 3: add block offsets, mirror to cursor, set sentinel ----
__global__ void k_scan3(int E) {
    int i = blockIdx.x * blockDim.x + threadIdx.x;
    if (i < NN) {
        int v = g_csr_ptr[i] + g_boff[i / SCAN_CHUNK];
        g_csr_ptr[i] = v;
        g_cursor[i]  = v;
    }
    if (i == 0) g_csr_ptr[NN] = E;
}

// ---- CSR fill: bucket {src, dinv_out[src]} by dst ----
__global__ void k_fill(const int* __restrict__ src, const int* __restrict__ dst, int E) {
    int e = blockIdx.x * blockDim.x + threadIdx.x;
    if (e < E) {
        int s = src[e];
        int pos = atomicAdd(&g_cursor[dst[e]], 1);
        g_csr_ent[pos] = make_int2(s, __float_as_int(g_dinv_out[s]));
    }
}

// ============================================================================
// HMMA GEMM: g_A[r][c] = fp16( X[r,:] @ W[:,c] )   (no scaling here)
// Block: 128 rows x 64 cols, 256 threads = 8 warps (4 m-groups x 2 n-groups).
// Each warp: 32x32 via 2x4 mma.m16n8k16 tiles. K chunked by 16.
// HALF_IN: X is g_B (half, stride 64); else fp32 Xf (stride K), converted.
// ============================================================================
template<int K, bool HALF_IN>
__global__ void k_gemm_tc(const float* __restrict__ Xf, int n) {
    __shared__ __align__(16) __half sX[128 * 16];  // [r][k], stride 16
    __shared__ __align__(16) __half sW[64 * 16];   // [n][k], stride 16

    const __half* __restrict__ Wt = (K == 128) ? g_W1t : g_W2t;

    int tid = threadIdx.x;
    int lane = tid & 31;
    int warp = tid >> 5;
    int warp_m = warp & 3;          // 0..3 -> rows warp_m*32
    int warp_n = warp >> 2;         // 0..1 -> cols warp_n*32
    int g = lane >> 2;              // 0..7
    int tig = lane & 3;             // 0..3
    int row0 = blockIdx.x * 128;

    float acc[2][4][4];
#pragma unroll
    for (int mt = 0; mt < 2; mt++)
#pragma unroll
        for (int nt = 0; nt < 4; nt++)
#pragma unroll
            for (int c = 0; c < 4; c++) acc[mt][nt][c] = 0.f;

    for (int kc = 0; kc < K; kc += 16) {
        // ---- load X chunk [128][16] ----
        if (HALF_IN) {
            // g_B half, row stride 64. 16B per thread (tid<256): 2048 halfs.
            int r = tid >> 1, part = tid & 1;
            int gr = row0 + r;
            if (gr < n) {
                *reinterpret_cast<uint4*>(&sX[r * 16 + part * 8]) =
                    *reinterpret_cast<const uint4*>(g_B + (size_t)gr * 64 + kc + part * 8);
            }
        } else {
#pragma unroll
            for (int p = 0; p < 2; p++) {
                int l = tid + p * 256;          // 0..511 float4 slots
                int r = l >> 2, c4 = l & 3;
                int gr = row0 + r;
                if (gr < n) {
                    float4 v = *reinterpret_cast<const float4*>(Xf + (size_t)gr * K + kc + c4 * 4);
                    __half2 h01 = __floats2half2_rn(v.x, v.y);
                    __half2 h23 = __floats2half2_rn(v.z, v.w);
                    *reinterpret_cast<__half2*>(&sX[r * 16 + c4 * 4])     = h01;
                    *reinterpret_cast<__half2*>(&sX[r * 16 + c4 * 4 + 2]) = h23;
                }
            }
        }
        // ---- load W chunk [64][16] (pre-transposed, half) ----
        if (tid < 128) {
            int nn_ = tid >> 1, part = tid & 1;
            *reinterpret_cast<uint4*>(&sW[nn_ * 16 + part * 8]) =
                *reinterpret_cast<const uint4*>(Wt + (size_t)nn_ * K + kc + part * 8);
        }
        __syncthreads();

#pragma unroll
        for (int mt = 0; mt < 2; mt++) {
            int ar = warp_m * 32 + mt * 16;
            unsigned a0 = *reinterpret_cast<unsigned*>(&sX[(ar + g) * 16 + tig * 2]);
            unsigned a1 = *reinterpret_cast<unsigned*>(&sX[(ar + g + 8) * 16 + tig * 2]);
            unsigned a2 = *reinterpret_cast<unsigned*>(&sX[(ar + g) * 16 + tig * 2 + 8]);
            unsigned a3 = *reinterpret_cast<unsigned*>(&sX[(ar + g + 8) * 16 + tig * 2 + 8]);
#pragma unroll
            for (int nt = 0; nt < 4; nt++) {
                int col = warp_n * 32 + nt * 8 + g;
                unsigned b0 = *reinterpret_cast<unsigned*>(&sW[col * 16 + tig * 2]);
                unsigned b1 = *reinterpret_cast<unsigned*>(&sW[col * 16 + tig * 2 + 8]);
                float* c = acc[mt][nt];
                asm volatile(
                    "mma.sync.aligned.m16n8k16.row.col.f32.f16.f16.f32 "
                    "{%0,%1,%2,%3},{%4,%5,%6,%7},{%8,%9},{%0,%1,%2,%3};"
                    : "+f"(c[0]), "+f"(c[1]), "+f"(c[2]), "+f"(c[3])
                    : "r"(a0), "r"(a1), "r"(a2), "r"(a3), "r"(b0), "r"(b1));
            }
        }
        __syncthreads();
    }

    // ---- epilogue: convert to half, store (no scaling) ----
#pragma unroll
    for (int mt = 0; mt < 2; mt++) {
        int row = row0 + warp_m * 32 + mt * 16 + g;
#pragma unroll
        for (int nt = 0; nt < 4; nt++) {
            int col = warp_n * 32 + nt * 8 + tig * 2;
            float* c = acc[mt][nt];
            if (row < n)
                *reinterpret_cast<__half2*>(g_A + (size_t)row * 64 + col) =
                    __floats2half2_rn(c[0], c[1]);
            if (row + 8 < n)
                *reinterpret_cast<__half2*>(g_A + (size_t)(row + 8) * 64 + col) =
                    __floats2half2_rn(c[2], c[3]);
        }
    }
}

// ============================================================================
// CSR aggregate + fused epilogue. Warp per node, lane owns 2 feature cols.
// acc = sum_src A[src]*dinv_out[src];  out = acc*din_inv + b  (relu if L1)
// ============================================================================
template<int LAYER>
__global__ void k_agg(const float* __restrict__ bias, float* __restrict__ outp, int n) {
    int gw = (blockIdx.x * blockDim.x + threadIdx.x) >> 5;
    int lane = threadIdx.x & 31;
    if (gw >= n) return;

    int s0 = g_csr_ptr[gw];
    int s1 = g_csr_ptr[gw + 1];

    float ax = 0.f, ay = 0.f;
    for (int base = s0; base < s1; base += 32) {
        int cnt = min(32, s1 - base);
        int2 ent = (lane < cnt) ? g_csr_ent[base + lane] : make_int2(0, 0);
        int e = ent.x;
        int dvb = ent.y;
        int j = 0;
        for (; j + 3 < cnt; j += 4) {
#pragma unroll
            for (int q = 0; q < 4; q++) {
                int s_q  = __shfl_sync(0xffffffffu, e, j + q);
                float dv = __int_as_float(__shfl_sync(0xffffffffu, dvb, j + q));
                __half2 h = *reinterpret_cast<const __half2*>(g_A + (size_t)s_q * 64 + lane * 2);
                float2 f = __half22float2(h);
                ax = fmaf(f.x, dv, ax);
                ay = fmaf(f.y, dv, ay);
            }
        }
        for (; j < cnt; j++) {
            int s_q  = __shfl_sync(0xffffffffu, e, j);
            float dv = __int_as_float(__shfl_sync(0xffffffffu, dvb, j));
            __half2 h = *reinterpret_cast<const __half2*>(g_A + (size_t)s_q * 64 + lane * 2);
            float2 f = __half22float2(h);
            ax = fmaf(f.x, dv, ax);
            ay = fmaf(f.y, dv, ay);
        }
    }

    float sc = g_dinv_in[gw];
    float ox = fmaf(ax, sc, bias[lane * 2]);
    float oy = fmaf(ay, sc, bias[lane * 2 + 1]);
    if (LAYER == 1) {
        ox = fmaxf(ox, 0.f);
        oy = fmaxf(oy, 0.f);
        *reinterpret_cast<__half2*>(g_B + (size_t)gw * 64 + lane * 2) = __floats2half2_rn(ox, oy);
    } else {
        *reinterpret_cast<float2*>(outp + (size_t)gw * 64 + lane * 2) = make_float2(ox, oy);
    }
}

extern "C" void kernel_launch(void* const* d_in, const int* in_sizes, int n_in,
                              void* d_out, int out_size) {
    const float* x   = (const float*)d_in[0];
    const int*   src = (const int*)d_in[1];
    const int*   dst = (const int*)d_in[2];
    const float* W1  = (const float*)d_in[3];
    const float* b1  = (const float*)d_in[4];
    const float* W2  = (const float*)d_in[5];
    const float* b2  = (const float*)d_in[6];
    float* out = (float*)d_out;

    const int n = NN;
    const int E = in_sizes[1];

    const int T = 256;
    int grid_edges = (E + T - 1) / T;
    int grid_nodes = (n + T - 1) / T;
    int grid_gemm  = (n + 127) / 128;
    int grid_agg   = (n * 32 + T - 1) / T;   // warp per node
    int grid_prepw = (64 * 128 + 64 * 64 + T - 1) / T;

    // graph prep + weight prep
    k_prepW<<<grid_prepw, T>>>(W1, W2);
    k_zero<<<grid_nodes, T>>>(n);
    k_deg<<<grid_edges, T>>>(src, dst, E);
    k_dinv<<<grid_nodes, T>>>(n);
    k_scan1<<<NBLK, 1024>>>();
    k_scan2<<<1, 64>>>();
    k_scan3<<<grid_nodes, T>>>(E);
    k_fill<<<grid_edges, T>>>(src, dst, E);

    // layer 1
    k_gemm_tc<128, false><<<grid_gemm, T>>>(x, n);
    k_agg<1><<<grid_agg, T>>>(b1, nullptr, n);

    // layer 2
    k_gemm_tc<64, true><<<grid_gemm, T>>>(nullptr, n);
    k_agg<2><<<grid_agg, T>>>(b2, out, n);
}